// round 13
// baseline (speedup 1.0000x reference)
#include <cuda_runtime.h>
#include <cstdint>

// Shapes (fixed): B=4, N=1024, C=64
#define B_ 4
#define N_ 1024
#define C_ 64
#define M_ (B_ * N_)
#define TI 8                  // i-rows per att tile (4 packed pairs)
#define NTILES 1024           // (N/TI) * 2 j-halves * B
#define PERSIST 740           // 5 blocks/SM * 148 SMs

typedef unsigned long long u64;

// Prepared projections: identity-path channels store tanh(proj), else raw.
// Channels 0..31: (d&7)>=5 identity (5:3). Channels 32..63: (d&7)>=4 (4:4).
__device__ float g_x1[M_ * C_];
__device__ float g_x2[M_ * C_];
__device__ float g_psum[M_ * 2];   // per-row partial softmax sums (2 j-halves)
__device__ int   g_ctr;            // work-stealing tile counter

__device__ __forceinline__ float tanh_fast(float x) {
    float y; asm("tanh.approx.f32 %0, %1;" : "=f"(y) : "f"(x)); return y;
}
__device__ __forceinline__ u64 pk(float lo, float hi) {
    u64 r; asm("mov.b64 %0, {%1, %2};" : "=l"(r) : "f"(lo), "f"(hi)); return r;
}
__device__ __forceinline__ float2 upk(u64 v) {
    float2 f; asm("mov.b64 {%0, %1}, %2;" : "=f"(f.x), "=f"(f.y) : "l"(v)); return f;
}
__device__ __forceinline__ u64 add2(u64 a, u64 b) {
    u64 r; asm("add.rn.f32x2 %0, %1, %2;" : "=l"(r) : "l"(a), "l"(b)); return r;
}
__device__ __forceinline__ u64 mul2(u64 a, u64 b) {
    u64 r; asm("mul.rn.f32x2 %0, %1, %2;" : "=l"(r) : "l"(a), "l"(b)); return r;
}
__device__ __forceinline__ u64 fma2(u64 a, u64 b, u64 c) {
    u64 r; asm("fma.rn.f32x2 %0, %1, %2, %3;" : "=l"(r) : "l"(a), "l"(b), "l"(c)); return r;
}
__device__ __forceinline__ u64 tanh2_mufu(u64 x) {
    u64 r;
    asm("{\n\t.reg .f32 a,b;\n\t"
        "mov.b64 {a,b}, %1;\n\t"
        "tanh.approx.f32 a, a;\n\t"
        "tanh.approx.f32 b, b;\n\t"
        "mov.b64 %0, {a,b};\n\t}" : "=l"(r) : "l"(x));
    return r;
}
__device__ __forceinline__ u64 rcp2_seed64(u64 d) {
    return 0x7EF311C37EF311C3ULL - d;
}
__device__ __forceinline__ u64 neg2(u64 x) { return x ^ 0x8000000080000000ULL; }

__device__ __forceinline__ bool is_identity_channel(int d) {
    return (d < 32) ? ((d & 7) >= 5) : ((d & 7) >= 4);
}

// ---------------------------------------------------------------------------
// Kernel 1: projections (also resets the tile counter for this graph replay).
// ---------------------------------------------------------------------------
__global__ __launch_bounds__(256) void proj_kernel(
    const float* __restrict__ x,
    const float* __restrict__ W1,
    const float* __restrict__ W2)
{
    __shared__ float W1s[C_ * 65];
    __shared__ float W2s[C_ * 65];
    __shared__ float xs[8 * C_];

    const int tid  = threadIdx.x;
    const int row0 = blockIdx.x * 8;

    if (blockIdx.x == 0 && tid == 0) g_ctr = 0;

    const float4* W1v = reinterpret_cast<const float4*>(W1);
    const float4* W2v = reinterpret_cast<const float4*>(W2);
    #pragma unroll
    for (int q = 0; q < 4; ++q) {
        int k4 = q * 256 + tid;
        int dd = k4 >> 4;
        int cc = (k4 & 15) * 4;
        float4 w1 = W1v[k4];
        float4 w2 = W2v[k4];
        float* p1 = W1s + dd * 65 + cc;
        float* p2 = W2s + dd * 65 + cc;
        p1[0] = w1.x; p1[1] = w1.y; p1[2] = w1.z; p1[3] = w1.w;
        p2[0] = w2.x; p2[1] = w2.y; p2[2] = w2.z; p2[3] = w2.w;
    }
    xs[tid]       = x[row0 * C_ + tid];
    xs[tid + 256] = x[row0 * C_ + tid + 256];
    __syncthreads();

    #pragma unroll
    for (int pp = 0; pp < 2; ++pp) {
        const int idx = pp * 256 + tid;
        const int r = idx >> 6, d = idx & 63;
        const float* xr = xs + r * C_;
        float a1 = 0.f, a2 = 0.f;
        #pragma unroll 8
        for (int c = 0; c < C_; ++c) {
            const float xv = xr[c];
            a1 = fmaf(xv, W1s[d * 65 + c], a1);
            a2 = fmaf(xv, W2s[d * 65 + c], a2);
        }
        const bool idp = is_identity_channel(d);
        g_x1[(row0 + r) * C_ + d] = idp ? tanh_fast(a1) : a1;
        g_x2[(row0 + r) * C_ + d] = idp ? tanh_fast(a2) : a2;
    }
}

// ---------------------------------------------------------------------------
// One 8-channel group on pre-loaded x2 values. KMUF channels via MUFU
// tanh(a+b); the rest via addition theorem on the FMA pipe (2-Newton recip).
// ---------------------------------------------------------------------------
template<int KMUF>
__device__ __forceinline__ void do_group(
    float4 v0, float4 v1, int g,
    const u64* __restrict__ x1p_s, const u64* __restrict__ w2s,
    u64 acc2[4], u64 ONE_, u64 TWO_)
{
    const float zs[8] = {v0.x, v0.y, v0.z, v0.w, v1.x, v1.y, v1.z, v1.w};

    #pragma unroll
    for (int k = 0; k < KMUF; ++k) {
        const int c = g * 8 + k;
        const u64 zz = pk(zs[k], zs[k]);
        const u64 wc = w2s[c];
        #pragma unroll
        for (int ip = 0; ip < 4; ++ip) {
            u64 s2 = add2(x1p_s[c * 4 + ip], zz);
            acc2[ip] = fma2(wc, tanh2_mufu(s2), acc2[ip]);
        }
    }
    #pragma unroll
    for (int k = KMUF; k < 8; ++k) {
        const int c = g * 8 + k;
        const u64 zz = pk(zs[k], zs[k]);
        const u64 wc = w2s[c];
        #pragma unroll
        for (int ip = 0; ip < 4; ++ip) {
            const u64 t1 = x1p_s[c * 4 + ip];
            u64 num = add2(t1, zz);
            u64 den = fma2(t1, zz, ONE_);
            u64 nd  = neg2(den);
            u64 r   = rcp2_seed64(den);
            u64 e   = fma2(nd, r, TWO_); r = mul2(r, e);
            e       = fma2(nd, r, TWO_); r = mul2(r, e);
            acc2[ip] = fma2(wc, mul2(num, r), acc2[ip]);
        }
    }
}

// ---------------------------------------------------------------------------
// Kernel 2: att mainloop — PERSISTENT blocks + atomic work stealing.
// 740 blocks (5/SM); each steals (b, jh, i0) tiles until the queue is empty.
// Tile = TI=8 i-rows x half the j range (512 j's, 2 chunks of 256).
// Channels 0..31 at 5:3 MUFU:identity, 32..63 at 4:4 (9:7 overall, pipes
// balanced). Depth-1 x2 prefetch. exp(att) straight to out; partials->g_psum.
// ---------------------------------------------------------------------------
__global__ __launch_bounds__(256, 5) void att_kernel(
    const float* __restrict__ w3,
    float* __restrict__ out)
{
    __shared__ u64  x1p_s[C_ * 4];
    __shared__ u64  w2s[C_];
    __shared__ float red[8][TI];
    __shared__ int  s_tile;

    const int tid  = threadIdx.x;
    const int lane = tid & 31;
    const int warp = tid >> 5;

    if (tid < C_) w2s[tid] = pk(w3[tid], w3[tid]);

    const u64 ONE_ = pk(1.0f, 1.0f);
    const u64 TWO_ = pk(2.0f, 2.0f);

    for (;;) {
        if (tid == 0) s_tile = atomicAdd(&g_ctr, 1);
        __syncthreads();                 // broadcast + protects x1p_s restage
        const int tile = s_tile;
        if (tile >= NTILES) return;

        // decode tile -> (b, jh, i0)
        const int b  = tile >> 8;              // 4 batches x 256 tiles
        const int t2 = tile & 255;
        const int jh = t2 >> 7;                // 2 j-halves
        const int i0 = (t2 & 127) * TI;

        {
            int c = tid >> 2, ip = tid & 3;
            const float* base = g_x1 + (size_t)(b * N_ + i0) * C_;
            x1p_s[tid] = pk(base[(2 * ip) * C_ + c], base[(2 * ip + 1) * C_ + c]);
        }
        __syncthreads();

        const float* x2b = g_x2 + (size_t)b * N_ * C_;

        float ps[TI];
        #pragma unroll
        for (int i = 0; i < TI; ++i) ps[i] = 0.f;

        for (int chunk = 0; chunk < 2; ++chunk) {
            const int j = jh * 512 + chunk * 256 + tid;
            const float4* xr = reinterpret_cast<const float4*>(x2b + (size_t)j * C_);

            u64 acc2[4] = {0ull, 0ull, 0ull, 0ull};

            float4 c0 = xr[0];
            float4 c1 = xr[1];

            for (int g = 0; g < 4; ++g) {            // channels 0..31: 5:3
                const int gn = g + 1;
                float4 n0 = xr[gn * 2];
                float4 n1 = xr[gn * 2 + 1];
                do_group<5>(c0, c1, g, x1p_s, w2s, acc2, ONE_, TWO_);
                c0 = n0; c1 = n1;
            }
            for (int g = 4; g < 8; ++g) {            // channels 32..63: 4:4
                const int gn = (g < 7) ? g + 1 : 7;
                float4 n0 = xr[gn * 2];
                float4 n1 = xr[gn * 2 + 1];
                do_group<4>(c0, c1, g, x1p_s, w2s, acc2, ONE_, TWO_);
                c0 = n0; c1 = n1;
            }

            #pragma unroll
            for (int ip = 0; ip < 4; ++ip) {
                float2 a = upk(acc2[ip]);
                float e0 = __expf(a.x);
                float e1 = __expf(a.y);
                out[((size_t)(b * N_ + i0 + 2 * ip))     * N_ + j] = e0;
                out[((size_t)(b * N_ + i0 + 2 * ip + 1)) * N_ + j] = e1;
                ps[2 * ip]     += e0;
                ps[2 * ip + 1] += e1;
            }
        }

        // ---- block reduction of per-row partial sums ----
        #pragma unroll
        for (int i = 0; i < TI; ++i) {
            #pragma unroll
            for (int o = 16; o > 0; o >>= 1)
                ps[i] += __shfl_xor_sync(0xFFFFFFFFu, ps[i], o);
            if (lane == 0) red[warp][i] = ps[i];
        }
        __syncthreads();
        if (tid < TI) {
            float s = 0.f;
            #pragma unroll
            for (int w = 0; w < 8; ++w) s += red[w][tid];
            g_psum[(size_t)(b * N_ + i0 + tid) * 2 + jh] = s;
        }
        // loop: next steal (syncthreads at top guards red/x1p reuse)
    }
}

// ---------------------------------------------------------------------------
// Kernel 3: normalize. 4096 blocks (one row) x 256 threads (one float4).
// ---------------------------------------------------------------------------
__global__ __launch_bounds__(256) void scale_kernel(float* __restrict__ out)
{
    const int row = blockIdx.x;
    const float s = g_psum[row * 2] + g_psum[row * 2 + 1];
    const float inv = __fdividef(1.f, s);
    float4* o = reinterpret_cast<float4*>(out + (size_t)row * N_);
    float4 v = o[threadIdx.x];
    v.x *= inv; v.y *= inv; v.z *= inv; v.w *= inv;
    o[threadIdx.x] = v;
}

extern "C" void kernel_launch(void* const* d_in, const int* in_sizes, int n_in,
                              void* d_out, int out_size)
{
    const float* x  = (const float*)d_in[0];
    const float* W1 = (const float*)d_in[1];
    const float* W2 = (const float*)d_in[2];
    const float* w3 = (const float*)d_in[3];
    float* out = (float*)d_out;

    proj_kernel<<<M_ / 8, 256>>>(x, W1, W2);

    att_kernel<<<PERSIST, 256>>>(w3, out);

    scale_kernel<<<M_, 256>>>(out);
}

// round 14
// speedup vs baseline: 1.0184x; 1.0184x over previous
#include <cuda_runtime.h>
#include <cstdint>

// Shapes (fixed): B=4, N=1024, C=64
#define B_ 4
#define N_ 1024
#define C_ 64
#define M_ (B_ * N_)
#define TI 8                  // i-rows per att tile (4 packed pairs)

typedef unsigned long long u64;

// Prepared projections: identity-path channels store tanh(proj), else raw.
// Channels 0..31: (d&7)>=5 identity (5:3). Channels 32..63: (d&7)>=4 (4:4).
__device__ float g_x1[M_ * C_];
__device__ float g_x2[M_ * C_];
__device__ float g_psum[M_ * 2];   // per-row partial softmax sums (2 j-halves)

__device__ __forceinline__ float tanh_fast(float x) {
    float y; asm("tanh.approx.f32 %0, %1;" : "=f"(y) : "f"(x)); return y;
}
__device__ __forceinline__ u64 pk(float lo, float hi) {
    u64 r; asm("mov.b64 %0, {%1, %2};" : "=l"(r) : "f"(lo), "f"(hi)); return r;
}
__device__ __forceinline__ float2 upk(u64 v) {
    float2 f; asm("mov.b64 {%0, %1}, %2;" : "=f"(f.x), "=f"(f.y) : "l"(v)); return f;
}
__device__ __forceinline__ u64 add2(u64 a, u64 b) {
    u64 r; asm("add.rn.f32x2 %0, %1, %2;" : "=l"(r) : "l"(a), "l"(b)); return r;
}
__device__ __forceinline__ u64 mul2(u64 a, u64 b) {
    u64 r; asm("mul.rn.f32x2 %0, %1, %2;" : "=l"(r) : "l"(a), "l"(b)); return r;
}
__device__ __forceinline__ u64 fma2(u64 a, u64 b, u64 c) {
    u64 r; asm("fma.rn.f32x2 %0, %1, %2, %3;" : "=l"(r) : "l"(a), "l"(b), "l"(c)); return r;
}
__device__ __forceinline__ u64 tanh2_mufu(u64 x) {
    u64 r;
    asm("{\n\t.reg .f32 a,b;\n\t"
        "mov.b64 {a,b}, %1;\n\t"
        "tanh.approx.f32 a, a;\n\t"
        "tanh.approx.f32 b, b;\n\t"
        "mov.b64 %0, {a,b};\n\t}" : "=l"(r) : "l"(x));
    return r;
}
__device__ __forceinline__ u64 rcp2_seed64(u64 d) {
    return 0x7EF311C37EF311C3ULL - d;
}
__device__ __forceinline__ u64 neg2(u64 x) { return x ^ 0x8000000080000000ULL; }

__device__ __forceinline__ bool is_identity_channel(int d) {
    return (d < 32) ? ((d & 7) >= 5) : ((d & 7) >= 4);
}

// ---------------------------------------------------------------------------
// Kernel 1: projections. 256 blocks x 256 thr, 16 rows per block (W staging
// amortized 2x vs R11). Coalesced float4 W stage -> padded smem; conflict-
// free LDS dot loop; identity channels store tanh(proj).
// ---------------------------------------------------------------------------
__global__ __launch_bounds__(256) void proj_kernel(
    const float* __restrict__ x,
    const float* __restrict__ W1,
    const float* __restrict__ W2)
{
    __shared__ float W1s[C_ * 65];
    __shared__ float W2s[C_ * 65];
    __shared__ float xs[16 * C_];

    const int tid  = threadIdx.x;
    const int row0 = blockIdx.x * 16;

    const float4* W1v = reinterpret_cast<const float4*>(W1);
    const float4* W2v = reinterpret_cast<const float4*>(W2);
    #pragma unroll
    for (int q = 0; q < 4; ++q) {
        int k4 = q * 256 + tid;
        int dd = k4 >> 4;
        int cc = (k4 & 15) * 4;
        float4 w1 = W1v[k4];
        float4 w2 = W2v[k4];
        float* p1 = W1s + dd * 65 + cc;
        float* p2 = W2s + dd * 65 + cc;
        p1[0] = w1.x; p1[1] = w1.y; p1[2] = w1.z; p1[3] = w1.w;
        p2[0] = w2.x; p2[1] = w2.y; p2[2] = w2.z; p2[3] = w2.w;
    }
    #pragma unroll
    for (int q = 0; q < 4; ++q)
        xs[q * 256 + tid] = x[row0 * C_ + q * 256 + tid];
    __syncthreads();

    #pragma unroll
    for (int pp = 0; pp < 4; ++pp) {
        const int idx = pp * 256 + tid;       // 0..1023 cells
        const int r = idx >> 6, d = idx & 63;
        const float* xr = xs + r * C_;
        float a1 = 0.f, a2 = 0.f;
        #pragma unroll 8
        for (int c = 0; c < C_; ++c) {
            const float xv = xr[c];
            a1 = fmaf(xv, W1s[d * 65 + c], a1);
            a2 = fmaf(xv, W2s[d * 65 + c], a2);
        }
        const bool idp = is_identity_channel(d);
        g_x1[(row0 + r) * C_ + d] = idp ? tanh_fast(a1) : a1;
        g_x2[(row0 + r) * C_ + d] = idp ? tanh_fast(a2) : a2;
    }
}

// ---------------------------------------------------------------------------
// One 8-channel group. KMUF channels via MUFU tanh(a+b); the rest via the
// addition theorem (t1+t2)/(1+t1*t2) on the FMA pipe (2-Newton recip).
// x2 loaded inline (TLP covers latency at 6 blocks/SM).
// ---------------------------------------------------------------------------
template<int KMUF>
__device__ __forceinline__ void do_group(
    const float4* __restrict__ xr, int g,
    const u64* __restrict__ x1p_s, const u64* __restrict__ w2s,
    u64 acc2[4], u64 ONE_, u64 TWO_)
{
    const float4 v0 = xr[g * 2];
    const float4 v1 = xr[g * 2 + 1];
    const float zs[8] = {v0.x, v0.y, v0.z, v0.w, v1.x, v1.y, v1.z, v1.w};

    #pragma unroll
    for (int k = 0; k < KMUF; ++k) {
        const int c = g * 8 + k;
        const u64 zz = pk(zs[k], zs[k]);
        const u64 wc = w2s[c];
        #pragma unroll
        for (int ip = 0; ip < 4; ++ip) {
            u64 s2 = add2(x1p_s[c * 4 + ip], zz);
            acc2[ip] = fma2(wc, tanh2_mufu(s2), acc2[ip]);
        }
    }
    #pragma unroll
    for (int k = KMUF; k < 8; ++k) {
        const int c = g * 8 + k;
        const u64 zz = pk(zs[k], zs[k]);
        const u64 wc = w2s[c];
        #pragma unroll
        for (int ip = 0; ip < 4; ++ip) {
            const u64 t1 = x1p_s[c * 4 + ip];
            u64 num = add2(t1, zz);
            u64 den = fma2(t1, zz, ONE_);
            u64 nd  = neg2(den);
            u64 r   = rcp2_seed64(den);
            u64 e   = fma2(nd, r, TWO_); r = mul2(r, e);
            e       = fma2(nd, r, TWO_); r = mul2(r, e);
            acc2[ip] = fma2(wc, mul2(num, r), acc2[ip]);
        }
    }
}

// ---------------------------------------------------------------------------
// Kernel 2: att mainloop. Grid (128, 2, 4) = 1024 blocks x 256 thr at
// SIX blocks/SM (reg cap 42; prefetch regs dropped — TLP covers L2 latency).
// Block owns TI=8 i-rows and half of j (512 j's, 2 chunks). Channels 0..31
// at 5:3 MUFU:identity, 32..63 at 4:4 (9:7 overall). exp(att) straight to
// out; per-row partials -> g_psum.
// ---------------------------------------------------------------------------
__global__ __launch_bounds__(256, 6) void att_kernel(
    const float* __restrict__ w3,
    float* __restrict__ out)
{
    __shared__ u64  x1p_s[C_ * 4];
    __shared__ u64  w2s[C_];
    __shared__ float red[8][TI];

    const int tid  = threadIdx.x;
    const int b    = blockIdx.z;
    const int jh   = blockIdx.y;
    const int i0   = blockIdx.x * TI;
    const int lane = tid & 31;
    const int warp = tid >> 5;

    {
        int c = tid >> 2, ip = tid & 3;
        const float* base = g_x1 + (size_t)(b * N_ + i0) * C_;
        x1p_s[tid] = pk(base[(2 * ip) * C_ + c], base[(2 * ip + 1) * C_ + c]);
    }
    if (tid < C_) w2s[tid] = pk(w3[tid], w3[tid]);
    __syncthreads();

    const u64 ONE_ = pk(1.0f, 1.0f);
    const u64 TWO_ = pk(2.0f, 2.0f);

    const float* x2b = g_x2 + (size_t)b * N_ * C_;

    float ps[TI];
    #pragma unroll
    for (int i = 0; i < TI; ++i) ps[i] = 0.f;

    for (int chunk = 0; chunk < 2; ++chunk) {
        const int j = jh * 512 + chunk * 256 + tid;
        const float4* xr = reinterpret_cast<const float4*>(x2b + (size_t)j * C_);

        u64 acc2[4] = {0ull, 0ull, 0ull, 0ull};

        for (int g = 0; g < 4; ++g)          // channels 0..31: 5:3
            do_group<5>(xr, g, x1p_s, w2s, acc2, ONE_, TWO_);
        for (int g = 4; g < 8; ++g)          // channels 32..63: 4:4
            do_group<4>(xr, g, x1p_s, w2s, acc2, ONE_, TWO_);

        // exp + direct store + per-row partials (no max pass: |att|<=sum|w3|)
        #pragma unroll
        for (int ip = 0; ip < 4; ++ip) {
            float2 a = upk(acc2[ip]);
            float e0 = __expf(a.x);
            float e1 = __expf(a.y);
            out[((size_t)(b * N_ + i0 + 2 * ip))     * N_ + j] = e0;
            out[((size_t)(b * N_ + i0 + 2 * ip + 1)) * N_ + j] = e1;
            ps[2 * ip]     += e0;
            ps[2 * ip + 1] += e1;
        }
    }

    // ---- block reduction of per-row partial sums ----
    #pragma unroll
    for (int i = 0; i < TI; ++i) {
        #pragma unroll
        for (int o = 16; o > 0; o >>= 1)
            ps[i] += __shfl_xor_sync(0xFFFFFFFFu, ps[i], o);
        if (lane == 0) red[warp][i] = ps[i];
    }
    __syncthreads();
    if (tid < TI) {
        float s = 0.f;
        #pragma unroll
        for (int w = 0; w < 8; ++w) s += red[w][tid];
        g_psum[(size_t)(b * N_ + i0 + tid) * 2 + jh] = s;
    }
}

// ---------------------------------------------------------------------------
// Kernel 3: normalize. 4096 blocks (one row) x 256 threads (one float4).
// ---------------------------------------------------------------------------
__global__ __launch_bounds__(256) void scale_kernel(float* __restrict__ out)
{
    const int row = blockIdx.x;
    const float s = g_psum[row * 2] + g_psum[row * 2 + 1];
    const float inv = __fdividef(1.f, s);
    float4* o = reinterpret_cast<float4*>(out + (size_t)row * N_);
    float4 v = o[threadIdx.x];
    v.x *= inv; v.y *= inv; v.z *= inv; v.w *= inv;
    o[threadIdx.x] = v;
}

extern "C" void kernel_launch(void* const* d_in, const int* in_sizes, int n_in,
                              void* d_out, int out_size)
{
    const float* x  = (const float*)d_in[0];
    const float* W1 = (const float*)d_in[1];
    const float* W2 = (const float*)d_in[2];
    const float* w3 = (const float*)d_in[3];
    float* out = (float*)d_out;

    proj_kernel<<<M_ / 16, 256>>>(x, W1, W2);

    dim3 grid(N_ / TI, 2, B_);
    att_kernel<<<grid, 256>>>(w3, out);

    scale_kernel<<<M_, 256>>>(out);
}

// round 15
// speedup vs baseline: 1.0491x; 1.0302x over previous
#include <cuda_runtime.h>
#include <cstdint>

// Shapes (fixed): B=4, N=1024, C=64
#define B_ 4
#define N_ 1024
#define C_ 64
#define M_ (B_ * N_)
#define TI 8                  // i-rows per att block (4 packed pairs)

typedef unsigned long long u64;

// Prepared projections: channel c with (c&7)>=5 stores tanh(proj), else raw.
__device__ float g_x1[M_ * C_];
__device__ float g_x2[M_ * C_];
__device__ float g_psum[M_ * 2];   // per-row partial softmax sums (2 j-halves)

__device__ __forceinline__ float tanh_fast(float x) {
    float y; asm("tanh.approx.f32 %0, %1;" : "=f"(y) : "f"(x)); return y;
}
__device__ __forceinline__ u64 pk(float lo, float hi) {
    u64 r; asm("mov.b64 %0, {%1, %2};" : "=l"(r) : "f"(lo), "f"(hi)); return r;
}
__device__ __forceinline__ float2 upk(u64 v) {
    float2 f; asm("mov.b64 {%0, %1}, %2;" : "=f"(f.x), "=f"(f.y) : "l"(v)); return f;
}
__device__ __forceinline__ u64 add2(u64 a, u64 b) {
    u64 r; asm("add.rn.f32x2 %0, %1, %2;" : "=l"(r) : "l"(a), "l"(b)); return r;
}
__device__ __forceinline__ u64 mul2(u64 a, u64 b) {
    u64 r; asm("mul.rn.f32x2 %0, %1, %2;" : "=l"(r) : "l"(a), "l"(b)); return r;
}
__device__ __forceinline__ u64 fma2(u64 a, u64 b, u64 c) {
    u64 r; asm("fma.rn.f32x2 %0, %1, %2, %3;" : "=l"(r) : "l"(a), "l"(b), "l"(c)); return r;
}
__device__ __forceinline__ u64 tanh2_mufu(u64 x) {
    u64 r;
    asm("{\n\t.reg .f32 a,b;\n\t"
        "mov.b64 {a,b}, %1;\n\t"
        "tanh.approx.f32 a, a;\n\t"
        "tanh.approx.f32 b, b;\n\t"
        "mov.b64 %0, {a,b};\n\t}" : "=l"(r) : "l"(x));
    return r;
}
__device__ __forceinline__ u64 rcp2_seed64(u64 d) {
    return 0x7EF311C37EF311C3ULL - d;
}
__device__ __forceinline__ u64 neg2(u64 x) { return x ^ 0x8000000080000000ULL; }

// ---------------------------------------------------------------------------
// Kernel 1: projections. 256 blocks x 256 thr, 16 rows per block. Coalesced
// float4 W stage -> padded smem; conflict-free LDS dot loop; channels
// (d&7)>=5 store tanh(proj)  [matches att's 5:3 split].
// ---------------------------------------------------------------------------
__global__ __launch_bounds__(256) void proj_kernel(
    const float* __restrict__ x,
    const float* __restrict__ W1,
    const float* __restrict__ W2)
{
    __shared__ float W1s[C_ * 65];
    __shared__ float W2s[C_ * 65];
    __shared__ float xs[16 * C_];

    const int tid  = threadIdx.x;
    const int row0 = blockIdx.x * 16;

    const float4* W1v = reinterpret_cast<const float4*>(W1);
    const float4* W2v = reinterpret_cast<const float4*>(W2);
    #pragma unroll
    for (int q = 0; q < 4; ++q) {
        int k4 = q * 256 + tid;
        int dd = k4 >> 4;
        int cc = (k4 & 15) * 4;
        float4 w1 = W1v[k4];
        float4 w2 = W2v[k4];
        float* p1 = W1s + dd * 65 + cc;
        float* p2 = W2s + dd * 65 + cc;
        p1[0] = w1.x; p1[1] = w1.y; p1[2] = w1.z; p1[3] = w1.w;
        p2[0] = w2.x; p2[1] = w2.y; p2[2] = w2.z; p2[3] = w2.w;
    }
    #pragma unroll
    for (int q = 0; q < 4; ++q)
        xs[q * 256 + tid] = x[row0 * C_ + q * 256 + tid];
    __syncthreads();

    #pragma unroll
    for (int pp = 0; pp < 4; ++pp) {
        const int idx = pp * 256 + tid;       // 0..1023 cells
        const int r = idx >> 6, d = idx & 63;
        const float* xr = xs + r * C_;
        float a1 = 0.f, a2 = 0.f;
        #pragma unroll 8
        for (int c = 0; c < C_; ++c) {
            const float xv = xr[c];
            a1 = fmaf(xv, W1s[d * 65 + c], a1);
            a2 = fmaf(xv, W2s[d * 65 + c], a2);
        }
        const bool idp = (d & 7) >= 5;
        g_x1[(row0 + r) * C_ + d] = idp ? tanh_fast(a1) : a1;
        g_x2[(row0 + r) * C_ + d] = idp ? tanh_fast(a2) : a2;
    }
}

// ---------------------------------------------------------------------------
// Kernel 2: att mainloop — EXACT R8 configuration (best measured).
// Grid (128, 2, 4) = 1024 blocks x 256 thr, lb(256,5). Block owns TI=8
// i-rows and half of j (512 j's, 2 chunks of 256). Per 8-channel group:
// 5 via MUFU tanh(a+b), 3 via addition theorem on FMA pipe (2-Newton recip).
// exp(att) straight to out; per-row partials -> g_psum.
// ---------------------------------------------------------------------------
__global__ __launch_bounds__(256, 5) void att_kernel(
    const float* __restrict__ w3,
    float* __restrict__ out)
{
    __shared__ u64  x1p_s[C_ * 4];     // [c*4+ip] = (prep1[2ip][c], prep1[2ip+1][c])
    __shared__ u64  w2s[C_];           // (w3[c], w3[c])
    __shared__ float red[8][TI];

    const int tid  = threadIdx.x;
    const int b    = blockIdx.z;
    const int jh   = blockIdx.y;       // j-half
    const int i0   = blockIdx.x * TI;
    const int lane = tid & 31;
    const int warp = tid >> 5;

    {
        int c = tid >> 2, ip = tid & 3;
        const float* base = g_x1 + (size_t)(b * N_ + i0) * C_;
        x1p_s[tid] = pk(base[(2 * ip) * C_ + c], base[(2 * ip + 1) * C_ + c]);
    }
    if (tid < C_) w2s[tid] = pk(w3[tid], w3[tid]);
    __syncthreads();

    const u64 ONE_ = pk(1.0f, 1.0f);
    const u64 TWO_ = pk(2.0f, 2.0f);

    const float* x2b = g_x2 + (size_t)b * N_ * C_;

    float ps[TI];
    #pragma unroll
    for (int i = 0; i < TI; ++i) ps[i] = 0.f;

    for (int chunk = 0; chunk < 2; ++chunk) {
        const int j = jh * 512 + chunk * 256 + tid;
        const float4* xr = reinterpret_cast<const float4*>(x2b + (size_t)j * C_);

        u64 acc2[4] = {0ull, 0ull, 0ull, 0ull};

        for (int g = 0; g < 8; ++g) {            // 8 channels per group
            const float4 v0 = xr[g * 2];
            const float4 v1 = xr[g * 2 + 1];
            const float zs[8] = {v0.x, v0.y, v0.z, v0.w, v1.x, v1.y, v1.z, v1.w};

            #pragma unroll
            for (int k = 0; k < 8; ++k) {
                const int c = g * 8 + k;
                const u64 zz = pk(zs[k], zs[k]);
                const u64 wc = w2s[c];
                if (k < 5) {
                    // MUFU channel (raw values)
                    #pragma unroll
                    for (int ip = 0; ip < 4; ++ip) {
                        u64 s2 = add2(x1p_s[c * 4 + ip], zz);
                        acc2[ip] = fma2(wc, tanh2_mufu(s2), acc2[ip]);
                    }
                } else {
                    // identity channel (pre-tanh'd values), 2-Newton recip
                    #pragma unroll
                    for (int ip = 0; ip < 4; ++ip) {
                        const u64 t1 = x1p_s[c * 4 + ip];
                        u64 num = add2(t1, zz);
                        u64 den = fma2(t1, zz, ONE_);
                        u64 nd  = neg2(den);
                        u64 r   = rcp2_seed64(den);
                        u64 e   = fma2(nd, r, TWO_); r = mul2(r, e);
                        e       = fma2(nd, r, TWO_); r = mul2(r, e);
                        acc2[ip] = fma2(wc, mul2(num, r), acc2[ip]);
                    }
                }
            }
        }
        // exp + direct store + per-row partials (no max pass: |att|<=sum|w3|)
        #pragma unroll
        for (int ip = 0; ip < 4; ++ip) {
            float2 a = upk(acc2[ip]);
            float e0 = __expf(a.x);
            float e1 = __expf(a.y);
            out[((size_t)(b * N_ + i0 + 2 * ip))     * N_ + j] = e0;
            out[((size_t)(b * N_ + i0 + 2 * ip + 1)) * N_ + j] = e1;
            ps[2 * ip]     += e0;
            ps[2 * ip + 1] += e1;
        }
    }

    // ---- block reduction of per-row partial sums ----
    #pragma unroll
    for (int i = 0; i < TI; ++i) {
        #pragma unroll
        for (int o = 16; o > 0; o >>= 1)
            ps[i] += __shfl_xor_sync(0xFFFFFFFFu, ps[i], o);
        if (lane == 0) red[warp][i] = ps[i];
    }
    __syncthreads();
    if (tid < TI) {
        float s = 0.f;
        #pragma unroll
        for (int w = 0; w < 8; ++w) s += red[w][tid];
        g_psum[(size_t)(b * N_ + i0 + tid) * 2 + jh] = s;
    }
}

// ---------------------------------------------------------------------------
// Kernel 3: normalize. 4096 blocks (one row) x 256 threads (one float4).
// ---------------------------------------------------------------------------
__global__ __launch_bounds__(256) void scale_kernel(float* __restrict__ out)
{
    const int row = blockIdx.x;
    const float s = g_psum[row * 2] + g_psum[row * 2 + 1];
    const float inv = __fdividef(1.f, s);
    float4* o = reinterpret_cast<float4*>(out + (size_t)row * N_);
    float4 v = o[threadIdx.x];
    v.x *= inv; v.y *= inv; v.z *= inv; v.w *= inv;
    o[threadIdx.x] = v;
}

extern "C" void kernel_launch(void* const* d_in, const int* in_sizes, int n_in,
                              void* d_out, int out_size)
{
    const float* x  = (const float*)d_in[0];
    const float* W1 = (const float*)d_in[1];
    const float* W2 = (const float*)d_in[2];
    const float* w3 = (const float*)d_in[3];
    float* out = (float*)d_out;

    proj_kernel<<<M_ / 16, 256>>>(x, W1, W2);

    dim3 grid(N_ / TI, 2, B_);
    att_kernel<<<grid, 256>>>(w3, out);

    scale_kernel<<<M_, 256>>>(out);
}

// round 16
// speedup vs baseline: 1.0794x; 1.0288x over previous
#include <cuda_runtime.h>
#include <cstdint>

// Shapes (fixed): B=4, N=1024, C=64
#define B_ 4
#define N_ 1024
#define C_ 64
#define M_ (B_ * N_)
#define TI 8                  // i-rows per att block (4 packed pairs)

typedef unsigned long long u64;

// Prepared projections: channel c with (c&7)>=5 stores tanh(proj), else raw.
__device__ float g_x1[M_ * C_];
__device__ float g_x2[M_ * C_];
__device__ float g_psum[M_ * 2];   // per-row partial softmax sums (2 j-halves)

__device__ __forceinline__ float tanh_fast(float x) {
    float y; asm("tanh.approx.f32 %0, %1;" : "=f"(y) : "f"(x)); return y;
}
__device__ __forceinline__ u64 pk(float lo, float hi) {
    u64 r; asm("mov.b64 %0, {%1, %2};" : "=l"(r) : "f"(lo), "f"(hi)); return r;
}
__device__ __forceinline__ float2 upk(u64 v) {
    float2 f; asm("mov.b64 {%0, %1}, %2;" : "=f"(f.x), "=f"(f.y) : "l"(v)); return f;
}
__device__ __forceinline__ u64 add2(u64 a, u64 b) {
    u64 r; asm("add.rn.f32x2 %0, %1, %2;" : "=l"(r) : "l"(a), "l"(b)); return r;
}
__device__ __forceinline__ u64 mul2(u64 a, u64 b) {
    u64 r; asm("mul.rn.f32x2 %0, %1, %2;" : "=l"(r) : "l"(a), "l"(b)); return r;
}
__device__ __forceinline__ u64 fma2(u64 a, u64 b, u64 c) {
    u64 r; asm("fma.rn.f32x2 %0, %1, %2, %3;" : "=l"(r) : "l"(a), "l"(b), "l"(c)); return r;
}
__device__ __forceinline__ u64 tanh2_mufu(u64 x) {
    u64 r;
    asm("{\n\t.reg .f32 a,b;\n\t"
        "mov.b64 {a,b}, %1;\n\t"
        "tanh.approx.f32 a, a;\n\t"
        "tanh.approx.f32 b, b;\n\t"
        "mov.b64 %0, {a,b};\n\t}" : "=l"(r) : "l"(x));
    return r;
}
__device__ __forceinline__ u64 rcp2_seed64(u64 d) {
    return 0x7EF311C37EF311C3ULL - d;
}
__device__ __forceinline__ u64 neg2(u64 x) { return x ^ 0x8000000080000000ULL; }

// ---------------------------------------------------------------------------
// Kernel 1: projections. 512 blocks x 256 thr, 8 rows per block.
// Register blocking: thread owns one d and TWO rows (rgrp, rgrp+4), so each
// W LDS pair is reused for both rows: 4 LDS + 4 FMA per (2 cells, c).
// Coalesced float4 W stage -> padded smem (stride 65, conflict-free).
// Channels (d&7)>=5 store tanh(proj) (identity-path prep for att).
// ---------------------------------------------------------------------------
__global__ __launch_bounds__(256) void proj_kernel(
    const float* __restrict__ x,
    const float* __restrict__ W1,
    const float* __restrict__ W2)
{
    __shared__ float W1s[C_ * 65];
    __shared__ float W2s[C_ * 65];
    __shared__ float xs[8 * C_];

    const int tid  = threadIdx.x;
    const int row0 = blockIdx.x * 8;
    const int d    = tid & 63;
    const int rg   = tid >> 6;        // 0..3 -> rows rg and rg+4

    const float4* W1v = reinterpret_cast<const float4*>(W1);
    const float4* W2v = reinterpret_cast<const float4*>(W2);
    #pragma unroll
    for (int q = 0; q < 4; ++q) {
        int k4 = q * 256 + tid;
        int dd = k4 >> 4;
        int cc = (k4 & 15) * 4;
        float4 w1 = W1v[k4];
        float4 w2 = W2v[k4];
        float* p1 = W1s + dd * 65 + cc;
        float* p2 = W2s + dd * 65 + cc;
        p1[0] = w1.x; p1[1] = w1.y; p1[2] = w1.z; p1[3] = w1.w;
        p2[0] = w2.x; p2[1] = w2.y; p2[2] = w2.z; p2[3] = w2.w;
    }
    xs[tid]       = x[row0 * C_ + tid];
    xs[tid + 256] = x[row0 * C_ + tid + 256];
    __syncthreads();

    const float* xrA = xs + rg * C_;          // row rg
    const float* xrB = xs + (rg + 4) * C_;    // row rg+4
    const float* w1r = W1s + d * 65;
    const float* w2r = W2s + d * 65;

    float a1A = 0.f, a2A = 0.f, a1B = 0.f, a2B = 0.f;
    #pragma unroll 8
    for (int c = 0; c < C_; ++c) {
        const float w1 = w1r[c];              // conflict-free LDS (reused 2x)
        const float w2 = w2r[c];
        const float xA = xrA[c];              // broadcast LDS
        const float xB = xrB[c];
        a1A = fmaf(xA, w1, a1A);
        a2A = fmaf(xA, w2, a2A);
        a1B = fmaf(xB, w1, a1B);
        a2B = fmaf(xB, w2, a2B);
    }

    const bool idp = (d & 7) >= 5;
    g_x1[(row0 + rg) * C_ + d]     = idp ? tanh_fast(a1A) : a1A;
    g_x2[(row0 + rg) * C_ + d]     = idp ? tanh_fast(a2A) : a2A;
    g_x1[(row0 + rg + 4) * C_ + d] = idp ? tanh_fast(a1B) : a1B;
    g_x2[(row0 + rg + 4) * C_ + d] = idp ? tanh_fast(a2B) : a2B;
}

// ---------------------------------------------------------------------------
// Kernel 2: att mainloop — FROZEN best configuration (R8/R15, 74.2us).
// Grid (128, 2, 4) = 1024 blocks x 256 thr, lb(256,5). Block owns TI=8
// i-rows and half of j (512 j's, 2 chunks of 256). Per 8-channel group:
// 5 via MUFU tanh(a+b), 3 via addition theorem on FMA pipe (2-Newton recip).
// exp(att) straight to out; per-row partials -> g_psum.
// ---------------------------------------------------------------------------
__global__ __launch_bounds__(256, 5) void att_kernel(
    const float* __restrict__ w3,
    float* __restrict__ out)
{
    __shared__ u64  x1p_s[C_ * 4];     // [c*4+ip] = (prep1[2ip][c], prep1[2ip+1][c])
    __shared__ u64  w2s[C_];           // (w3[c], w3[c])
    __shared__ float red[8][TI];

    const int tid  = threadIdx.x;
    const int b    = blockIdx.z;
    const int jh   = blockIdx.y;       // j-half
    const int i0   = blockIdx.x * TI;
    const int lane = tid & 31;
    const int warp = tid >> 5;

    {
        int c = tid >> 2, ip = tid & 3;
        const float* base = g_x1 + (size_t)(b * N_ + i0) * C_;
        x1p_s[tid] = pk(base[(2 * ip) * C_ + c], base[(2 * ip + 1) * C_ + c]);
    }
    if (tid < C_) w2s[tid] = pk(w3[tid], w3[tid]);
    __syncthreads();

    const u64 ONE_ = pk(1.0f, 1.0f);
    const u64 TWO_ = pk(2.0f, 2.0f);

    const float* x2b = g_x2 + (size_t)b * N_ * C_;

    float ps[TI];
    #pragma unroll
    for (int i = 0; i < TI; ++i) ps[i] = 0.f;

    for (int chunk = 0; chunk < 2; ++chunk) {
        const int j = jh * 512 + chunk * 256 + tid;
        const float4* xr = reinterpret_cast<const float4*>(x2b + (size_t)j * C_);

        u64 acc2[4] = {0ull, 0ull, 0ull, 0ull};

        for (int g = 0; g < 8; ++g) {            // 8 channels per group
            const float4 v0 = xr[g * 2];
            const float4 v1 = xr[g * 2 + 1];
            const float zs[8] = {v0.x, v0.y, v0.z, v0.w, v1.x, v1.y, v1.z, v1.w};

            #pragma unroll
            for (int k = 0; k < 8; ++k) {
                const int c = g * 8 + k;
                const u64 zz = pk(zs[k], zs[k]);
                const u64 wc = w2s[c];
                if (k < 5) {
                    // MUFU channel (raw values)
                    #pragma unroll
                    for (int ip = 0; ip < 4; ++ip) {
                        u64 s2 = add2(x1p_s[c * 4 + ip], zz);
                        acc2[ip] = fma2(wc, tanh2_mufu(s2), acc2[ip]);
                    }
                } else {
                    // identity channel (pre-tanh'd values), 2-Newton recip
                    #pragma unroll
                    for (int ip = 0; ip < 4; ++ip) {
                        const u64 t1 = x1p_s[c * 4 + ip];
                        u64 num = add2(t1, zz);
                        u64 den = fma2(t1, zz, ONE_);
                        u64 nd  = neg2(den);
                        u64 r   = rcp2_seed64(den);
                        u64 e   = fma2(nd, r, TWO_); r = mul2(r, e);
                        e       = fma2(nd, r, TWO_); r = mul2(r, e);
                        acc2[ip] = fma2(wc, mul2(num, r), acc2[ip]);
                    }
                }
            }
        }
        // exp + direct store + per-row partials (no max pass: |att|<=sum|w3|)
        #pragma unroll
        for (int ip = 0; ip < 4; ++ip) {
            float2 a = upk(acc2[ip]);
            float e0 = __expf(a.x);
            float e1 = __expf(a.y);
            out[((size_t)(b * N_ + i0 + 2 * ip))     * N_ + j] = e0;
            out[((size_t)(b * N_ + i0 + 2 * ip + 1)) * N_ + j] = e1;
            ps[2 * ip]     += e0;
            ps[2 * ip + 1] += e1;
        }
    }

    // ---- block reduction of per-row partial sums ----
    #pragma unroll
    for (int i = 0; i < TI; ++i) {
        #pragma unroll
        for (int o = 16; o > 0; o >>= 1)
            ps[i] += __shfl_xor_sync(0xFFFFFFFFu, ps[i], o);
        if (lane == 0) red[warp][i] = ps[i];
    }
    __syncthreads();
    if (tid < TI) {
        float s = 0.f;
        #pragma unroll
        for (int w = 0; w < 8; ++w) s += red[w][tid];
        g_psum[(size_t)(b * N_ + i0 + tid) * 2 + jh] = s;
    }
}

// ---------------------------------------------------------------------------
// Kernel 3: normalize. 4096 blocks (one row) x 256 threads (one float4).
// ---------------------------------------------------------------------------
__global__ __launch_bounds__(256) void scale_kernel(float* __restrict__ out)
{
    const int row = blockIdx.x;
    const float s = g_psum[row * 2] + g_psum[row * 2 + 1];
    const float inv = __fdividef(1.f, s);
    float4* o = reinterpret_cast<float4*>(out + (size_t)row * N_);
    float4 v = o[threadIdx.x];
    v.x *= inv; v.y *= inv; v.z *= inv; v.w *= inv;
    o[threadIdx.x] = v;
}

extern "C" void kernel_launch(void* const* d_in, const int* in_sizes, int n_in,
                              void* d_out, int out_size)
{
    const float* x  = (const float*)d_in[0];
    const float* W1 = (const float*)d_in[1];
    const float* W2 = (const float*)d_in[2];
    const float* w3 = (const float*)d_in[3];
    float* out = (float*)d_out;

    proj_kernel<<<M_ / 8, 256>>>(x, W1, W2);

    dim3 grid(N_ / TI, 2, B_);
    att_kernel<<<grid, 256>>>(w3, out);

    scale_kernel<<<M_, 256>>>(out);
}